// round 2
// baseline (speedup 1.0000x reference)
#include <cuda_runtime.h>
#include <cstdint>

// CTC forward (alpha recursion) in log2 domain — exact mirror of the
// reference's logaddexp recursion. One block per batch element, one thread
// per CTC state (thread 0 also carries top state S-1). Alphas double-buffered
// in shared memory; single __syncthreads per timestep. Emission probabilities
// prefetched PF steps ahead through a register queue.

#define PF   16
#define NEG2 (-1e30f)
#define EPSF 1e-7f
#define LN2F 0.6931471805599453f

__device__ __forceinline__ float ex2f(float x) {
    float r; asm("ex2.approx.ftz.f32 %0, %1;" : "=f"(r) : "f"(x)); return r;
}
__device__ __forceinline__ float lg2f(float x) {
    float r; asm("lg2.approx.ftz.f32 %0, %1;" : "=f"(r) : "f"(x)); return r;
}

__global__ void ctc_fwd_kernel(const int* __restrict__ y_true,
                               const float* __restrict__ y_pred,
                               const int* __restrict__ in_len,
                               const int* __restrict__ lab_len,
                               float* __restrict__ out,
                               int T, int C, int Lmax)
{
    extern __shared__ float smem[];
    const int S = 2 * Lmax + 1;                 // 129
    float* bufA = smem;                         // alpha[s] stored at [s+2]
    float* bufB = smem + (S + 2);

    const int b        = blockIdx.x;
    const int tid      = threadIdx.x;           // 0 .. 2*Lmax-1
    const int s        = tid;
    const int nthreads = blockDim.x;

    const int L = lab_len[b];
    int Tl = in_len[b];
    if (Tl > T) Tl = T;
    if (Tl < 1) Tl = 1;

    const int blank = C - 1;
    const float* yp = y_pred + (size_t)b * (size_t)T * (size_t)C;
    const int*   yt = y_true + (size_t)b * (size_t)Lmax;

    // Static per-state properties
    const int  lab   = (s & 1) ? yt[s >> 1] : blank;
    const bool valid = (s < 2 * L + 1);
    const bool skip  = (s & 1) && (s >= 3) && (yt[s >> 1] != yt[(s >> 1) - 1]);
    const bool doTop = (tid == 0);
    const bool topValid = (L == Lmax);          // state S-1 valid iff 128 < 2L+1

    const float* pbase = yp + lab;

    // ---- init buffers ----
    for (int i = tid; i < 2 * (S + 2); i += nthreads) smem[i] = NEG2;
    __syncthreads();

    // ---- t = 0 ----
    float p0  = __ldg(pbase);
    float e0  = lg2f(p0 + EPSF);
    float myA = (valid && s <= 1) ? e0 : NEG2;  // alpha[0], alpha[1]
    float aTop = NEG2;                          // alpha[S-1] (carried by tid 0)

    float* prev = bufA;
    float* cur  = bufB;
    prev[s + 2] = myA;                          // pads [0],[1] stay NEG2
    __syncthreads();

    // ---- prefetch queue (raw probabilities) ----
    float q[PF];
#pragma unroll
    for (int i = 0; i < PF; ++i) {
        int tt = 1 + i;
        q[i] = (tt < Tl) ? __ldg(pbase + (size_t)tt * (size_t)C) : 0.0f;
    }

    // ---- main recursion t = 1 .. Tl-1 ----
    for (int t0 = 1; t0 < Tl; t0 += PF) {
#pragma unroll
        for (int i = 0; i < PF; ++i) {
            int t = t0 + i;
            if (t >= Tl) break;

            float p  = q[i];
            int   tn = t + PF;
            q[i] = (tn < Tl) ? __ldg(pbase + (size_t)tn * (size_t)C) : 0.0f;

            // emission in log2 (off critical path)
            float e2  = lg2f(p + EPSF);
            float e2v = valid ? e2 : NEG2;

            float a1 = myA;
            float a2 = prev[s + 1];                  // alpha[s-1]
            float a3 = skip ? prev[s] : NEG2;        // alpha[s-2] (masked)

            float m   = fmaxf(a1, fmaxf(a2, a3));
            float sum = ex2f(a1 - m) + ex2f(a2 - m) + ex2f(a3 - m);
            float nw  = m + lg2f(sum) + e2v;
            myA = nw;
            cur[s + 2] = nw;

            if (doTop) {                              // state S-1: blank, no skip
                float b1 = aTop;
                float b2 = prev[S];                   // alpha[S-2]
                float mt = fmaxf(b1, b2);
                float st = ex2f(b1 - mt) + ex2f(b2 - mt);
                float eT = topValid ? e2 : NEG2;      // tid0's p IS blank prob
                aTop = mt + lg2f(st) + eT;
                cur[S + 1] = aTop;
            }
            __syncthreads();
            float* tb = prev; prev = cur; cur = tb;
        }
    }

    // ---- finalize: -logaddexp(alpha[2L], alpha[2L-1]) ----
    if (tid == 0) {
        float al = prev[2 * L + 2];
        float ap = (L > 0) ? prev[2 * L + 1] : NEG2;
        float m  = fmaxf(al, ap);
        float ll2 = m + lg2f(ex2f(al - m) + ex2f(ap - m));
        out[b] = -(ll2 * LN2F);
    }
}

extern "C" void kernel_launch(void* const* d_in, const int* in_sizes, int n_in,
                              void* d_out, int out_size)
{
    (void)n_in; (void)out_size;
    const int*   y_true  = (const int*)  d_in[0];
    const float* y_pred  = (const float*)d_in[1];
    const int*   in_len  = (const int*)  d_in[2];
    const int*   lab_len = (const int*)  d_in[3];
    float*       out     = (float*)      d_out;

    const int B    = in_sizes[2];              // input_length has B elements
    const int Lmax = in_sizes[0] / B;          // 64
    const int C    = 256;
    const int T    = in_sizes[1] / (B * C);    // 1024

    const int S       = 2 * Lmax + 1;
    const int threads = 2 * Lmax;              // 128
    const size_t shmem = (size_t)(2 * (S + 2)) * sizeof(float);

    ctc_fwd_kernel<<<B, threads, shmem>>>(y_true, y_pred, in_len, lab_len, out,
                                          T, C, Lmax);
}

// round 3
// speedup vs baseline: 4.6364x; 4.6364x over previous
#include <cuda_runtime.h>
#include <cstdint>

// CTC forward in log2 domain.
// Block = 256 threads: warp 0 = compute warp (129 CTC states, 4 per lane,
// lane 31 carries the 129th), warps 1..7 = emission loaders that gather
// y_pred, convert to masked log2-emissions, and stage tiles of TT timesteps
// in double-buffered shared memory. One __syncthreads per TT steps; the
// recursion itself uses only registers + one shfl per step.

#define TT    32
#define ROWP  132
#define NEG2  (-1e30f)
#define EPSF  1e-7f
#define LN2F  0.6931471805599453f

__device__ __forceinline__ float ex2f(float x) {
    float r; asm("ex2.approx.ftz.f32 %0, %1;" : "=f"(r) : "f"(x)); return r;
}
__device__ __forceinline__ float lg2f(float x) {
    float r; asm("lg2.approx.ftz.f32 %0, %1;" : "=f"(r) : "f"(x)); return r;
}

__global__ void __launch_bounds__(256, 1)
ctc_fwd_kernel(const int* __restrict__ yt_g,
               const float* __restrict__ yp_g,
               const int* __restrict__ in_len,
               const int* __restrict__ lab_len,
               float* __restrict__ out,
               int T, int C, int Lmax)
{
    __shared__ float etile[2][TT][ROWP];   // log2-emissions, [buf][t_local][s]
    __shared__ float fin[ROWP];            // final alphas

    const int b   = blockIdx.x;
    const int tid = threadIdx.x;
    const int S   = 2 * Lmax + 1;          // 129

    const int L = lab_len[b];
    int Tl = in_len[b];
    if (Tl > T) Tl = T;
    if (Tl < 1) Tl = 1;

    const int blank = C - 1;
    const float* yp = yp_g + (size_t)b * (size_t)T * (size_t)C;
    const int*   yt = yt_g + (size_t)b * (size_t)Lmax;

    const bool isCompute = (tid < 32);
    const int  lane = tid & 31;

    // ---- loader per-thread constants (one state column per loader thread) ----
    const int  lt        = tid - 32;                    // 0..223
    const bool actLoader = (!isCompute) && (lt < S);
    const float* colp = yp;
    bool valThread = false;
    if (actLoader) {
        int labv  = (lt & 1) ? yt[lt >> 1] : blank;
        valThread = (lt < 2 * L + 1);
        colp      = yp + labv;
    }

    auto load_tile = [&](int tile, int bi) {
        if (!actLoader) return;
        const int t0 = tile * TT;
#pragma unroll 8
        for (int i = 0; i < TT; ++i) {
            float p = __ldg(colp + (size_t)(t0 + i) * (size_t)C);
            etile[bi][i][lt] = valThread ? lg2f(p + EPSF) : NEG2;
        }
    };

    // ---- compute per-thread constants ----
    float a0 = NEG2, a1 = NEG2, a2 = NEG2, a3 = NEG2, a4 = NEG2;
    bool skip1 = false, skip3 = false;
    if (isCompute) {
        int l1 = __ldg(yt + 2 * lane);            // label of state 4k+1
        int l3 = __ldg(yt + 2 * lane + 1);        // label of state 4k+3
        skip1 = (lane >= 1) ? (l1 != __ldg(yt + 2 * lane - 1)) : false;
        skip3 = (l3 != l1);
    }

    // ---- preload tile 0 ----
    if (!isCompute) load_tile(0, 0);
    __syncthreads();

    const int nTiles = (T + TT - 1) / TT;

    for (int tile = 0; tile < nTiles; ++tile) {
        const int bi = tile & 1;
        if (!isCompute) {
            if (tile + 1 < nTiles) load_tile(tile + 1, (tile + 1) & 1);
        } else {
            const int t0 = tile * TT;
            if (t0 < Tl) {
                int i0 = 0;
                if (tile == 0) {
                    // t = 0 init: alpha[0]=e0[0], alpha[1]=e0[1] (mask in e),
                    // everything else NEG.
                    const float4 e4 = *(const float4*)&etile[0][0][4 * lane];
                    if (lane == 0) { a0 = e4.x; a1 = e4.y; }
                    i0 = 1;
                }
#pragma unroll 4
                for (int i = i0; i < TT; ++i) {
                    const int t = t0 + i;
                    if (t >= Tl) break;                       // uniform

                    const float4 e4 = *(const float4*)&etile[bi][i][4 * lane];
                    const float eTop = (lane == 31) ? etile[bi][i][128] : NEG2;

                    float n3 = __shfl_up_sync(0xffffffffu, a3, 1);  // a[4k-1]
                    if (lane == 0) n3 = NEG2;

                    // s = 4k (blank): terms a0, n3
                    float m0 = fmaxf(a0, n3);
                    float r0 = m0 + lg2f(ex2f(a0 - m0) + ex2f(n3 - m0)) + e4.x;

                    // s = 4k+1 (label): terms a1, a0, skip1? n3
                    float sk1 = skip1 ? n3 : NEG2;
                    float m1  = fmaxf(a1, fmaxf(a0, sk1));
                    float r1  = m1 + lg2f(ex2f(a1 - m1) + ex2f(a0 - m1)
                                          + ex2f(sk1 - m1)) + e4.y;

                    // s = 4k+2 (blank): terms a2, a1
                    float m2 = fmaxf(a2, a1);
                    float r2 = m2 + lg2f(ex2f(a2 - m2) + ex2f(a1 - m2)) + e4.z;

                    // s = 4k+3 (label): terms a3, a2, skip3? a1
                    float sk3 = skip3 ? a1 : NEG2;
                    float m3  = fmaxf(a3, fmaxf(a2, sk3));
                    float r3  = m3 + lg2f(ex2f(a3 - m3) + ex2f(a2 - m3)
                                          + ex2f(sk3 - m3)) + e4.w;

                    // s = 128 (blank, lane 31 only): terms a4, a3
                    float m4 = fmaxf(a4, a3);
                    float r4 = m4 + lg2f(ex2f(a4 - m4) + ex2f(a3 - m4)) + eTop;

                    a0 = r0; a1 = r1; a2 = r2; a3 = r3; a4 = r4;
                }
            }
        }
        __syncthreads();
    }

    // ---- finalize: -ln(logaddexp(alpha[2L], alpha[2L-1])) ----
    if (isCompute) {
        *(float4*)&fin[4 * lane] = make_float4(a0, a1, a2, a3);
        if (lane == 31) fin[128] = a4;
        __syncwarp();
        if (lane == 0) {
            float al = fin[2 * L];
            float ap = (L > 0) ? fin[2 * L - 1] : NEG2;
            float m  = fmaxf(al, ap);
            float ll2 = m + lg2f(ex2f(al - m) + ex2f(ap - m));
            out[b] = -(ll2 * LN2F);
        }
    }
}

extern "C" void kernel_launch(void* const* d_in, const int* in_sizes, int n_in,
                              void* d_out, int out_size)
{
    (void)n_in; (void)out_size;
    const int*   y_true  = (const int*)  d_in[0];
    const float* y_pred  = (const float*)d_in[1];
    const int*   in_len  = (const int*)  d_in[2];
    const int*   lab_len = (const int*)  d_in[3];
    float*       out     = (float*)      d_out;

    const int B    = in_sizes[2];              // input_length has B elements
    const int Lmax = in_sizes[0] / B;          // 64
    const int C    = 256;
    const int T    = in_sizes[1] / (B * C);    // 1024

    ctc_fwd_kernel<<<B, 256>>>(y_true, y_pred, in_len, lab_len, out, T, C, Lmax);
}